// round 1
// baseline (speedup 1.0000x reference)
#include <cuda_runtime.h>
#include <cuda_bf16.h>

// LoongSpike fractional-SSM Vandermonde kernel.
// K[ch=0, h, l] = 2 * Re( sum_{n=0..63} C_disc[h,n] * exp(dtA[h,n])^l )
// Implemented as a geometric recurrence: w <- w * r, one complex FMA-mul +
// real accumulate per (state, l).  Compute-bound on the fp32 FMA pipe.

#define Hh      512
#define NSTc    32
#define LCc     32      // l-elements per thread (register accumulator)
#define CPBc    32      // chunks per block  -> block covers CPBc*LCc = 1024 l
#define NSTATES 64      // M*NST complex states
#define GRPS    8
#define GS      8

__global__ __launch_bounds__(32) void loong_spike_kernel(
    const float* __restrict__ C_real,      // [1, H, NST, 2]
    const float* __restrict__ log_dt,      // [H]
    const float* __restrict__ log_A_real,  // [H, NST]
    const float* __restrict__ A_imag,      // [H, NST]
    const float* __restrict__ omega_logit, // [2]
    const float* __restrict__ eta_logit,   // [2]
    float* __restrict__ out,               // [1, H, L]
    int L)
{
    __shared__ float2 W0[NSTATES][CPBc + 1];  // chunk-start values, padded pitch
    __shared__ float2 Rs[NSTATES];            // per-state step ratio r = exp(dtA)

    const int tid = threadIdx.x;              // 0..31
    const int h   = blockIdx.y;
    const int bx  = blockIdx.x;
    const int l0_base = bx * (CPBc * LCc);

    // ---------------- Phase 1: per-state setup + chunk-start table ---------
    const float dt = expf(log_dt[h]);
    #pragma unroll
    for (int s = 0; s < 2; ++s) {
        const int nst = tid;
        const int n   = s * NSTc + tid;       // n = m*NST + nst

        const float Are = -expf(log_A_real[h * NSTc + nst]);
        const float Aim = A_imag[h * NSTc + nst];

        const float ol = omega_logit[s];
        const float el = eta_logit[s];
        const float omega = 1e-6f + (1.0f / (1.0f + expf(-ol))) * (100.0f - 1e-6f);
        const float eta   = 1e-6f + (1.0f / (1.0f + expf(-el))) * (10.0f  - 1e-6f);

        const float Afr = -omega + eta * Are;     // A_frac (complex)
        const float Afi = eta * Aim;
        const float Cre = eta * C_real[(h * NSTc + nst) * 2 + 0];  // C_frac
        const float Cim = eta * C_real[(h * NSTc + nst) * 2 + 1];

        const float dr = Afr * dt;                // dtA
        const float di = Afi * dt;

        // r = exp(dtA)  (also exp_dtA for the discretization)
        float er, sn, cs;
        er = expf(dr);
        sincosf(di, &sn, &cs);
        const float rre = er * cs;
        const float rim = er * sn;

        // C_disc = C_frac * (exp_dtA - 1) / (A_frac + 1e-8)   (or * dt if tiny)
        float Cdre, Cdim;
        const float mag2 = Afr * Afr + Afi * Afi;
        if (mag2 < 1e-12f) {
            Cdre = Cre * dt;
            Cdim = Cim * dt;
        } else {
            const float nre = rre - 1.0f, nim = rim;
            const float tre = Cre * nre - Cim * nim;
            const float tim = Cre * nim + Cim * nre;
            const float dre = Afr + 1e-8f, dim = Afi;
            const float inv = 1.0f / (dre * dre + dim * dim);
            Cdre = (tre * dre + tim * dim) * inv;
            Cdim = (tim * dre - tre * dim) * inv;
        }

        // chunk-start value at l0_base: w = C_disc * exp(dtA * l0_base)
        const float p = (float)l0_base;
        float ssn, scs;
        const float serx = expf(dr * p);
        sincosf(di * p, &ssn, &scs);
        const float Sre = serx * scs, Sim = serx * ssn;
        float wre = Cdre * Sre - Cdim * Sim;
        float wim = Cdre * Sim + Cdim * Sre;

        // per-chunk advance R = exp(dtA * LC)
        float sL, cL;
        const float erL = expf(dr * (float)LCc);
        sincosf(di * (float)LCc, &sL, &cL);
        const float Rre = erL * cL, Rim = erL * sL;

        Rs[n] = make_float2(rre, rim);
        #pragma unroll 1
        for (int ci = 0; ci < CPBc; ++ci) {
            W0[n][ci] = make_float2(wre, wim);
            const float t1 = wre * Rre - wim * Rim;
            const float t2 = wre * Rim + wim * Rre;
            wre = t1; wim = t2;
        }
    }
    __syncthreads();

    // ---------------- Phase 2: recurrence sweep -----------------------------
    const int ci = tid;
    const int l0 = l0_base + ci * LCc;
    if (l0 >= L) return;

    float acc[LCc];
    #pragma unroll
    for (int l = 0; l < LCc; ++l) acc[l] = 0.0f;

    #pragma unroll 1
    for (int g = 0; g < GRPS; ++g) {
        float wr[GS], wi[GS], rr[GS], ri[GS];
        #pragma unroll
        for (int j = 0; j < GS; ++j) {
            const float2 w = W0[g * GS + j][ci];
            const float2 r = Rs[g * GS + j];
            wr[j] = w.x; wi[j] = w.y; rr[j] = r.x; ri[j] = r.y;
        }
        #pragma unroll
        for (int l = 0; l < LCc; ++l) {
            #pragma unroll
            for (int j = 0; j < GS; ++j) {
                acc[l] += wr[j];                                  // Re at l
                const float t1 = wr[j] * rr[j] - wi[j] * ri[j];   // w *= r
                const float t2 = wr[j] * ri[j] + wi[j] * rr[j];
                wr[j] = t1; wi[j] = t2;
            }
        }
    }

    float* op = out + (size_t)h * L + l0;
    if (l0 + LCc <= L) {
        #pragma unroll
        for (int l = 0; l < LCc; l += 4) {
            float4 v = make_float4(2.0f * acc[l],     2.0f * acc[l + 1],
                                   2.0f * acc[l + 2], 2.0f * acc[l + 3]);
            *reinterpret_cast<float4*>(op + l) = v;
        }
    } else {
        for (int l = 0; l < LCc && l0 + l < L; ++l) op[l] = 2.0f * acc[l];
    }
}

extern "C" void kernel_launch(void* const* d_in, const int* in_sizes, int n_in,
                              void* d_out, int out_size) {
    const float* C_real      = (const float*)d_in[0];
    const float* log_dt      = (const float*)d_in[1];
    const float* log_A_real  = (const float*)d_in[2];
    const float* A_imag      = (const float*)d_in[3];
    const float* omega_logit = (const float*)d_in[4];
    const float* eta_logit   = (const float*)d_in[5];
    float* out = (float*)d_out;

    const int L  = out_size / Hh;                 // CH == 1
    const int Lc = (L + LCc - 1) / LCc;           // total chunks
    const int gx = (Lc + CPBc - 1) / CPBc;        // blocks along l

    dim3 grid(gx, Hh);
    loong_spike_kernel<<<grid, 32>>>(C_real, log_dt, log_A_real, A_imag,
                                     omega_logit, eta_logit, out, L);
}